// round 3
// baseline (speedup 1.0000x reference)
#include <cuda_runtime.h>
#include <math.h>

#define D_PTS   2562
#define D_PAD   2624          // padded row count for W (41*64)
#define F_BINS  513
#define P_PAIRS 36
#define KDEG    32
#define PK      (P_PAIRS*KDEG)   // 1152
#define BT_N    1000
#define BT_PAD  1024
#define YP      D_PAD             // Y row stride == padded column count
#define TAU_M   4.67

// ---------------- scratch (static __device__ — no allocations) ----------------
__device__ float g_Ac[F_BINS*KDEG];
__device__ float g_As[F_BINS*KDEG];
__device__ float g_M[(size_t)BT_PAD*PK];     // moments   [bt][p*32+k]
__device__ float g_W[(size_t)D_PAD*PK];      // Cheb vals [d][p*32+k]
__device__ float g_Y[(size_t)BT_PAD*YP];     // scores    [bt][d]

__device__ const int c_i0[P_PAIRS] = {0,0,0,0,0,0,0,0, 1,1,1,1,1,1,1, 2,2,2,2,2,2,
                                      3,3,3,3,3, 4,4,4,4, 5,5,5, 6,6, 7};
__device__ const int c_i1[P_PAIRS] = {0,1,2,3,4,5,6,7, 1,2,3,4,5,6,7, 2,3,4,5,6,7,
                                      3,4,5,6,7, 4,5,6,7, 5,6,7, 6,7, 7};

// ---------------- Stage A1: Chebyshev coefficients of cos/sin(omega_f * tau) ----
// cos(c*u) ~ sum_k Ac_k T_k(u) on u in [-1,1], via 64-node Chebyshev DCT (fp64).
__global__ void k_coeff() {
    __shared__ double vc[64], vs[64];
    const double PI = 3.141592653589793238462643;
    int f = blockIdx.x;
    int n = threadIdx.x;
    double c = (2.0 * PI * (double)f / 1024.0) * (double)TAU_M;
    double theta = PI * (n + 0.5) / 64.0;
    double x = cos(theta);
    double sn, cn;
    sincos(c * x, &sn, &cn);
    vc[n] = cn; vs[n] = sn;
    __syncthreads();
    int k = threadIdx.x;
    if (k < KDEG) {
        // cos(k*theta_n), theta_n arithmetic in n -> 3-term recurrence
        double delta = (PI / 64.0) * (double)k;
        double c0 = cos(0.5 * delta);
        double c1 = cos(1.5 * delta);
        double mult = 2.0 * cos(delta);
        double sc = vc[0]*c0 + vc[1]*c1;
        double ss = vs[0]*c0 + vs[1]*c1;
        double cp = c0, cc = c1;
        for (int nn = 2; nn < 64; nn++) {
            double cnx = mult*cc - cp;
            sc += vc[nn]*cnx; ss += vs[nn]*cnx;
            cp = cc; cc = cnx;
        }
        double scale = (k == 0 ? 1.0 : 2.0) / 64.0;
        g_Ac[f*KDEG + k] = (float)(sc * scale);
        g_As[f*KDEG + k] = (float)(ss * scale);
    }
}

// ---------------- Stage A2: T_k(u_{d,p}) table --------------------------------
__global__ void k_w2(const float* __restrict__ taus, int D) {
    int idx = blockIdx.x * blockDim.x + threadIdx.x;
    if (idx >= D * P_PAIRS) return;
    int d = idx / P_PAIRS, p = idx - d * P_PAIRS;
    float u = (taus[d*8 + c_i0[p]] - taus[d*8 + c_i1[p]]) * (float)(1.0 / TAU_M);
    float* w = g_W + (size_t)d * PK + p * KDEG;
    float tp = 1.0f, tc = u;
    w[0] = 1.0f; w[1] = u;
    float u2 = 2.0f * u;
#pragma unroll
    for (int kk = 2; kk < KDEG; kk++) {
        float tn = fmaf(u2, tc, -tp);
        w[kk] = tn; tp = tc; tc = tn;
    }
}

// ---------------- Stage B: PHAT normalize + moments ----------------------------
// M[bt][p*32+k] = sum_f Xr_n[bt,f,p]*Ac[f,k] + Xi_n[bt,f,p]*As[f,k]
// Block = one bt, 288 threads: k = tid&31, pg = tid>>5 (9 groups of 4 pairs).
__global__ void __launch_bounds__(288) k_moment(const float* __restrict__ X) {
    __shared__ __align__(16) float raw[8*72];
    __shared__ __align__(16) float Xr_s[8][36];
    __shared__ __align__(16) float Xi_s[8][36];
    __shared__ __align__(16) float Ac_s[256];
    __shared__ __align__(16) float As_s[256];

    int bt  = blockIdx.x;
    int tid = threadIdx.x;
    int k   = tid & 31;
    int pg  = tid >> 5;   // 0..8
    float a0 = 0.f, a1 = 0.f, a2 = 0.f, a3 = 0.f;
    const float* Xb = X + (size_t)bt * (F_BINS * 72);

    for (int f0 = 0; f0 < F_BINS; f0 += 8) {
        int nf = F_BINS - f0; if (nf > 8) nf = 8;
        __syncthreads();
        int tot = nf * 72;
        for (int t = tid; t < tot; t += 288) raw[t] = Xb[f0*72 + t];
        int na = nf * 32;
        if (tid < na) {
            Ac_s[tid] = g_Ac[f0*32 + tid];
            As_s[tid] = g_As[f0*32 + tid];
        }
        __syncthreads();
        if (tid < nf * 36) {
            int ff = tid / 36, p = tid - ff * 36;
            float re = raw[ff*72 + p];
            float im = raw[ff*72 + 36 + p];
            float s  = fmaf(re, re, im * im);
            float inv = rsqrtf(fmaxf(s, 1e-36f));
            Xr_s[ff][p] = re * inv;
            Xi_s[ff][p] = im * inv;
        }
        __syncthreads();
#pragma unroll 8
        for (int ff = 0; ff < nf; ff++) {
            float ac  = Ac_s[ff*32 + k];
            float as_ = As_s[ff*32 + k];
            float4 xr = *(const float4*)&Xr_s[ff][pg*4];
            float4 xi = *(const float4*)&Xi_s[ff][pg*4];
            a0 = fmaf(xr.x, ac, fmaf(xi.x, as_, a0));
            a1 = fmaf(xr.y, ac, fmaf(xi.y, as_, a1));
            a2 = fmaf(xr.z, ac, fmaf(xi.z, as_, a2));
            a3 = fmaf(xr.w, ac, fmaf(xi.w, as_, a3));
        }
    }
    float* Mo = g_M + (size_t)bt * PK + k;
    Mo[(pg*4 + 0)*32] = a0;
    Mo[(pg*4 + 1)*32] = a1;
    Mo[(pg*4 + 2)*32] = a2;
    Mo[(pg*4 + 3)*32] = a3;
}

// ---------------- Stage C: Ys = M (1000x1152) * W^T (1152x2562) ----------------
// 64x64 tile, 256 threads, 4x4 per-thread microtile, 2-deep global prefetch.
#define KC 16
__global__ void __launch_bounds__(256) k_gemm() {
    __shared__ __align__(16) float Ms[KC][68];
    __shared__ __align__(16) float Ws[KC][68];
    int d0 = blockIdx.x * 64;
    int m0 = blockIdx.y * 64;
    int tid = threadIdx.x;
    int tx = tid & 15, ty = tid >> 4;
    int lr = tid >> 2;          // 0..63
    int lk = (tid & 3) * 4;     // 0,4,8,12
    const float* Mg = g_M + (size_t)(m0 + lr) * PK + lk;
    const float* Wg = g_W + (size_t)(d0 + lr) * PK + lk;
    float acc[4][4] = {};

    float4 mv = *(const float4*)(Mg);
    float4 wv = *(const float4*)(Wg);

    for (int k0 = 0; k0 < PK; k0 += KC) {
        Ms[lk+0][lr] = mv.x; Ms[lk+1][lr] = mv.y; Ms[lk+2][lr] = mv.z; Ms[lk+3][lr] = mv.w;
        Ws[lk+0][lr] = wv.x; Ws[lk+1][lr] = wv.y; Ws[lk+2][lr] = wv.z; Ws[lk+3][lr] = wv.w;
        __syncthreads();
        if (k0 + KC < PK) {          // prefetch next slice while FMAs run
            mv = *(const float4*)(Mg + k0 + KC);
            wv = *(const float4*)(Wg + k0 + KC);
        }
#pragma unroll
        for (int kk = 0; kk < KC; kk++) {
            float4 a = *(const float4*)&Ms[kk][ty*4];
            float4 b = *(const float4*)&Ws[kk][tx*4];
            acc[0][0] = fmaf(a.x, b.x, acc[0][0]);
            acc[0][1] = fmaf(a.x, b.y, acc[0][1]);
            acc[0][2] = fmaf(a.x, b.z, acc[0][2]);
            acc[0][3] = fmaf(a.x, b.w, acc[0][3]);
            acc[1][0] = fmaf(a.y, b.x, acc[1][0]);
            acc[1][1] = fmaf(a.y, b.y, acc[1][1]);
            acc[1][2] = fmaf(a.y, b.z, acc[1][2]);
            acc[1][3] = fmaf(a.y, b.w, acc[1][3]);
            acc[2][0] = fmaf(a.z, b.x, acc[2][0]);
            acc[2][1] = fmaf(a.z, b.y, acc[2][1]);
            acc[2][2] = fmaf(a.z, b.z, acc[2][2]);
            acc[2][3] = fmaf(a.z, b.w, acc[2][3]);
            acc[3][0] = fmaf(a.w, b.x, acc[3][0]);
            acc[3][1] = fmaf(a.w, b.y, acc[3][1]);
            acc[3][2] = fmaf(a.w, b.z, acc[3][2]);
            acc[3][3] = fmaf(a.w, b.w, acc[3][3]);
        }
        __syncthreads();
    }
#pragma unroll
    for (int ii = 0; ii < 4; ii++) {
        float4 v = make_float4(acc[ii][0], acc[ii][1], acc[ii][2], acc[ii][3]);
        *(float4*)(g_Y + (size_t)(m0 + ty*4 + ii) * YP + d0 + tx*4) = v;
    }
}

// ---------------- Stage D: argmax over D + gather doas -------------------------
__global__ void __launch_bounds__(256) k_argmax(const float* __restrict__ doas,
                                                float* __restrict__ out, int D) {
    __shared__ float sv[256];
    __shared__ int   si[256];
    int bt = blockIdx.x, tid = threadIdx.x;
    const float* y = g_Y + (size_t)bt * YP;
    float bv = -3.4e38f; int bi = 0;
    for (int d = tid; d < D; d += 256) {
        float v = y[d];
        if (v > bv) { bv = v; bi = d; }
    }
    sv[tid] = bv; si[tid] = bi;
    __syncthreads();
    for (int s = 128; s > 0; s >>= 1) {
        if (tid < s) {
            float v2 = sv[tid + s]; int i2 = si[tid + s];
            if (v2 > sv[tid] || (v2 == sv[tid] && i2 < si[tid])) { sv[tid] = v2; si[tid] = i2; }
        }
        __syncthreads();
    }
    if (tid < 3) out[bt*3 + tid] = doas[si[0]*3 + tid];
}

// ---------------- launch -------------------------------------------------------
extern "C" void kernel_launch(void* const* d_in, const int* in_sizes, int n_in,
                              void* d_out, int out_size) {
    const float* XXs  = (const float*)d_in[0];
    const float* taus = (const float*)d_in[1];
    const float* doas = (const float*)d_in[2];
    float* out = (float*)d_out;

    int D  = in_sizes[1] / 8;            if (D  > D_PTS) D  = D_PTS;
    int BT = in_sizes[0] / (F_BINS*72);  if (BT > BT_N)  BT = BT_N;

    k_coeff<<<F_BINS, 64>>>();
    k_w2<<<(D * P_PAIRS + 255) / 256, 256>>>(taus, D);
    k_moment<<<BT, 288>>>(XXs);
    dim3 g((D + 63) / 64, (BT + 63) / 64);
    k_gemm<<<g, 256>>>();
    k_argmax<<<BT, 256>>>(doas, out, D);
}